// round 10
// baseline (speedup 1.0000x reference)
#include <cuda_runtime.h>
#include <cuda_fp16.h>
#include <cstdint>
#include <cstddef>

#define T_STEPS 256
#define BATCH   32
#define EMB     256
#define LAT     512
#define OUT_DIM 32000
#define MROWS   (T_STEPS * BATCH)   // 8192

// ---------------- device scratch (no allocations allowed) ------------------
__device__ float    g_xproj[(size_t)MROWS * LAT];      // 16 MB
__device__ __half   g_hA[(size_t)MROWS * LAT];         // 8 MB, A fragment-major fp16
__device__ __half   g_WoB[(size_t)OUT_DIM * LAT];      // 32.75 MB, B fragment-major fp16
__device__ unsigned g_cnt[8];                           // rnn barrier counters

// ---------------- helpers ----------------------------------------------------
__device__ __forceinline__ unsigned long long pack2(float a, float b) {
    unsigned long long r;
    asm("mov.b64 %0, {%1, %2};" : "=l"(r) : "f"(a), "f"(b));
    return r;
}
__device__ __forceinline__ void unpack2(unsigned long long v, float& a, float& b) {
    asm("mov.b64 {%0, %1}, %2;" : "=f"(a), "=f"(b) : "l"(v));
}
__device__ __forceinline__ void ffma2(unsigned long long& acc, unsigned long long h,
                                      unsigned long long w) {
    asm("fma.rn.f32x2 %0, %1, %2, %0;" : "+l"(acc) : "l"(h), "l"(w));
}
__device__ __forceinline__ uint32_t pack_h2(float lo, float hi) {
    __half2 h = __floats2half2_rn(lo, hi);
    return *(uint32_t*)&h;
}
__device__ __forceinline__ uint32_t smaddr(const void* p) {
    return (uint32_t)__cvta_generic_to_shared(p);
}
__device__ __forceinline__ uint32_t elect_one_pred() {
    uint32_t pred;
    asm volatile(
        "{\n\t.reg .pred p;\n\t"
        "elect.sync _|p, 0xFFFFFFFF;\n\t"
        "selp.b32 %0, 1, 0, p;\n\t}"
        : "=r"(pred));
    return pred;
}
__device__ __forceinline__ void lds128(uint32_t a, uint32_t& r0, uint32_t& r1,
                                       uint32_t& r2, uint32_t& r3) {
    asm volatile("ld.shared.v4.b32 {%0, %1, %2, %3}, [%4];"
                 : "=r"(r0), "=r"(r1), "=r"(r2), "=r"(r3) : "r"(a));
}
__device__ __forceinline__ void bulk_g2s(uint32_t dst, const void* src,
                                         uint32_t bytes, uint32_t mbar) {
    asm volatile(
        "cp.async.bulk.shared::cluster.global.mbarrier::complete_tx::bytes "
        "[%0], [%1], %2, [%3];"
        :: "r"(dst), "l"(src), "r"(bytes), "r"(mbar) : "memory");
}
__device__ __forceinline__ void red_release_add(unsigned* p, unsigned v) {
    asm volatile("red.release.gpu.global.add.u32 [%0], %1;"
                 :: "l"(p), "r"(v) : "memory");
}
__device__ __forceinline__ unsigned ld_acquire(const unsigned* p) {
    unsigned v;
    asm volatile("ld.global.acquire.gpu.u32 %0, [%1];" : "=r"(v) : "l"(p) : "memory");
    return v;
}
#define MBARRIER_INIT(mbar, cnt) \
    asm volatile("mbarrier.init.shared.b64 [%0], %1;" \
                 :: "r"((uint32_t)(mbar)), "r"((uint32_t)(cnt)) : "memory")
#define MBARRIER_ARRIVE(mbar) \
    asm volatile("mbarrier.arrive.shared.b64 _, [%0];" \
                 :: "r"((uint32_t)(mbar)) : "memory")
#define MBARRIER_EXPECT_TX(mbar, tx) \
    asm volatile("mbarrier.arrive.expect_tx.shared.b64 _, [%0], %1;" \
                 :: "r"((uint32_t)(mbar)), "r"((uint32_t)(tx)) : "memory")
#define MBARRIER_WAIT_PARITY(mbar, par) do {                                   \
    uint32_t _m = (uint32_t)(mbar);                                            \
    uint32_t _p = (uint32_t)(par);                                             \
    asm volatile(                                                              \
        "{\n\t.reg .pred P1;\n\t"                                              \
        "WL_%=:\n\t"                                                           \
        "mbarrier.try_wait.parity.acquire.cta.shared::cta.b64 P1, [%0], %1, 0x989680;\n\t" \
        "@P1 bra.uni WD_%=;\n\t"                                               \
        "bra.uni WL_%=;\n\t"                                                   \
        "WD_%=:\n\t}"                                                          \
        :: "r"(_m), "r"(_p) : "memory");                                       \
} while (0)
#define FENCE_ASYNC_SHARED() asm volatile("fence.proxy.async.shared::cta;" ::: "memory")

__device__ __forceinline__ void mma_f16(float& c0, float& c1, float& c2, float& c3,
                                        uint32_t a0, uint32_t a1, uint32_t a2, uint32_t a3,
                                        uint32_t b0, uint32_t b1) {
    asm volatile(
        "mma.sync.aligned.m16n8k16.row.col.f32.f16.f16.f32 "
        "{%0,%1,%2,%3}, {%4,%5,%6,%7}, {%8,%9}, {%0,%1,%2,%3};"
        : "+f"(c0), "+f"(c1), "+f"(c2), "+f"(c3)
        : "r"(a0), "r"(a1), "r"(a2), "r"(a3), "r"(b0), "r"(b1));
}

// ============================================================================
// Kernel 1: xproj = gather(emb, x) @ W_h[:256] + b_h  (fp32 SIMT)
// ============================================================================
__global__ void __launch_bounds__(256) k_xproj(const int* __restrict__ x,
                                               const float* __restrict__ emb,
                                               const float* __restrict__ Wh,
                                               const float* __restrict__ bh)
{
    __shared__ float As[64][36];
    __shared__ float Bs[32][132];
    __shared__ int   xs[64];

    const int tid = threadIdx.x;
    const int m0  = blockIdx.y * 64;
    const int n0  = blockIdx.x * 128;

    if (blockIdx.x == 0 && blockIdx.y == 0 && tid < 8) g_cnt[tid] = 0;

    if (tid < 64) xs[tid] = x[m0 + tid];
    __syncthreads();

    const int ty = tid >> 5;
    const int tx = tid & 31;

    float acc[8][4];
#pragma unroll
    for (int i = 0; i < 8; i++)
#pragma unroll
        for (int j = 0; j < 4; j++) acc[i][j] = 0.f;

    for (int k0 = 0; k0 < EMB; k0 += 32) {
#pragma unroll
        for (int q = 0; q < 2; q++) {
            int f = tid + q * 256;
            int r = f >> 3, c4 = f & 7;
            float4 v = *(const float4*)(emb + (size_t)xs[r] * EMB + k0 + c4 * 4);
            *(float4*)(&As[r][c4 * 4]) = v;
        }
#pragma unroll
        for (int q = 0; q < 4; q++) {
            int f = tid + q * 256;
            int r = f >> 5, c4 = f & 31;
            float4 v = *(const float4*)(Wh + (size_t)(k0 + r) * LAT + n0 + c4 * 4);
            *(float4*)(&Bs[r][c4 * 4]) = v;
        }
        __syncthreads();

#pragma unroll
        for (int kq = 0; kq < 8; kq++) {
            float bt[4][4];
#pragma unroll
            for (int kk = 0; kk < 4; kk++) {
                float4 t = *(float4*)(&Bs[kq * 4 + kk][tx * 4]);
                bt[kk][0] = t.x; bt[kk][1] = t.y; bt[kk][2] = t.z; bt[kk][3] = t.w;
            }
#pragma unroll
            for (int i = 0; i < 8; i++) {
                float4 a4 = *(float4*)(&As[ty * 8 + i][kq * 4]);
#pragma unroll
                for (int j = 0; j < 4; j++) {
                    acc[i][j] = fmaf(a4.x, bt[0][j],
                                fmaf(a4.y, bt[1][j],
                                fmaf(a4.z, bt[2][j],
                                fmaf(a4.w, bt[3][j], acc[i][j]))));
                }
            }
        }
        __syncthreads();
    }

    float4 bh4 = *(const float4*)(bh + n0 + tx * 4);
#pragma unroll
    for (int i = 0; i < 8; i++) {
        float4 o;
        o.x = acc[i][0] + bh4.x;
        o.y = acc[i][1] + bh4.y;
        o.z = acc[i][2] + bh4.z;
        o.w = acc[i][3] + bh4.w;
        *(float4*)(g_xproj + (size_t)(m0 + ty * 8 + i) * LAT + n0 + tx * 4) = o;
    }
}

// ============================================================================
// Kernel 1b: build g_WoB — B fragment-major fp16 for m16n8k16.
// ============================================================================
__global__ void __launch_bounds__(256) k_prepB(const float* __restrict__ Wo)
{
    const int nt = blockIdx.x, kt = blockIdx.y;
    const int w = threadIdx.x >> 5, lane = threadIdx.x & 31;
    __half* panel = g_WoB + ((size_t)nt * 16 + kt) * 8192;

#pragma unroll
    for (int bi = 0; bi < 4; bi++) {
        int b  = w * 4 + bi;                 // 0..31
        int wn = b >> 3, kk = (b >> 2) & 1, np = b & 3;
        int n0 = nt * 256 + wn * 64 + np * 16 + (lane >> 2);
        int k0 = kt * 32 + kk * 16 + (lane & 3) * 2;
        const float* base = Wo + (size_t)k0 * OUT_DIM + n0;
        uint4 v;
        v.x = pack_h2(base[0],                       base[(size_t)1 * OUT_DIM]);
        v.y = pack_h2(base[(size_t)8 * OUT_DIM],     base[(size_t)9 * OUT_DIM]);
        v.z = pack_h2(base[8],                       base[(size_t)1 * OUT_DIM + 8]);
        v.w = pack_h2(base[(size_t)8 * OUT_DIM + 8], base[(size_t)9 * OUT_DIM + 8]);
        *(uint4*)(panel + (size_t)b * 256 + lane * 8) = v;
    }
}

// ============================================================================
// Kernel 2: persistent recurrence (round-7 sync shape). g_hA writes REMOVED
// from the critical loop — only coalesced fp32 hid stores before the release.
// ============================================================================
__global__ void __launch_bounds__(256, 1) k_rnn(const float* __restrict__ Wh,
                                                float* __restrict__ hid)
{
    __shared__ ulonglong2 hsT[512];
    __shared__ float      red[8][4][32];

    const int tid  = threadIdx.x;
    const int s    = tid >> 5;
    const int c    = tid & 31;
    const int bgrp = blockIdx.x >> 4;
    const int cgrp = blockIdx.x & 15;
    const int b0   = bgrp * 4;
    const int col  = cgrp * 32 + c;

    float w[64];
#pragma unroll
    for (int i = 0; i < 64; i++)
        w[i] = Wh[(size_t)(EMB + s * 64 + i) * LAT + col];

    unsigned target = 0;
    for (int t = 0; t < T_STEPS; t++) {
        float xp = 0.f;
        if (tid < 128) {
            xp = __ldg(g_xproj + (size_t)(t * BATCH + b0 + (tid >> 5)) * LAT
                       + cgrp * 32 + (tid & 31));
        }

#pragma unroll
        for (int hq = 0; hq < 2; hq++) {
            int k = tid + hq * 256;
            float v0, v1, v2, v3;
            if (t == 0) {
                v0 = v1 = v2 = v3 = 0.f;
            } else {
                const float* hp = hid + (size_t)((t - 1) * BATCH + b0) * LAT + k;
                v0 = __ldcg(hp);
                v1 = __ldcg(hp + LAT);
                v2 = __ldcg(hp + 2 * LAT);
                v3 = __ldcg(hp + 3 * LAT);
            }
            hsT[k] = make_ulonglong2(pack2(v0, v1), pack2(v2, v3));
        }
        __syncthreads();

        unsigned long long acc01 = 0ull, acc23 = 0ull;
        const ulonglong2* hp = hsT + s * 64;
#pragma unroll
        for (int i = 0; i < 64; i++) {
            ulonglong2 hv = hp[i];
            unsigned long long w2 = pack2(w[i], w[i]);
            ffma2(acc01, hv.x, w2);
            ffma2(acc23, hv.y, w2);
        }
        float a0, a1, a2, a3;
        unpack2(acc01, a0, a1);
        unpack2(acc23, a2, a3);
        red[s][0][c] = a0;
        red[s][1][c] = a1;
        red[s][2][c] = a2;
        red[s][3][c] = a3;
        __syncthreads();

        if (tid < 128) {
            int bb = tid >> 5, cc = tid & 31;
            float v = xp;
#pragma unroll
            for (int ss = 0; ss < 8; ss++) v += red[ss][bb][cc];
            int colw = cgrp * 32 + cc;
            int rowi = t * BATCH + b0 + bb;
            v = fmaxf(v, 0.f);
            hid[(size_t)rowi * LAT + colw] = v;   // coalesced fp32 only
        }
        __syncthreads();

        target += 16;
        if (tid == 0) {
            red_release_add(&g_cnt[bgrp], 1u);
            while (ld_acquire(&g_cnt[bgrp]) < target) { }
        }
        __syncthreads();
    }
}

// ============================================================================
// Kernel 2b: k_prepA — build g_hA (fragment-major fp16) from hid, coalesced.
// Panel (mt, kt) = 4096 halfs. Grid (64, 16), 256 threads (warp w = mi16).
// For kk in {0,1}: lane emits uint4 = 4 uint32 (j=0..3), each = half pair
//   row  = mt*128 + w*16 + (lane>>2) + 8*(j&1)
//   kbase= kt*32 + kk*16 + (lane&3)*2 + 8*(j>>1)
//   pair = (hid[row][kbase], hid[row][kbase+1])
// ============================================================================
__global__ void __launch_bounds__(256) k_prepA(const float* __restrict__ hid)
{
    const int mt = blockIdx.x, kt = blockIdx.y;
    const int w = threadIdx.x >> 5, lane = threadIdx.x & 31;
    __half* panel = g_hA + ((size_t)mt * 16 + kt) * 4096;

#pragma unroll
    for (int kk = 0; kk < 2; kk++) {
        uint32_t r4[4];
#pragma unroll
        for (int j = 0; j < 4; j++) {
            int row   = mt * 128 + w * 16 + (lane >> 2) + 8 * (j & 1);
            int kbase = kt * 32 + kk * 16 + (lane & 3) * 2 + 8 * (j >> 1);
            float2 v = *(const float2*)(hid + (size_t)row * LAT + kbase);
            r4[j] = pack_h2(v.x, v.y);
        }
        *(uint4*)(panel + (size_t)(((w * 2 + kk) * 32 + lane) * 4) * 2) =
            make_uint4(r4[0], r4[1], r4[2], r4[3]);
    }
}

// ============================================================================
// Kernel 3: out = hid @ Wo + bo (unchanged from round 9).
// ============================================================================
#define NSTG 6
#define A_PANEL_B 8192u
#define B_PANEL_B 8192u
#define STG_B (A_PANEL_B + B_PANEL_B)            // 16384
#define TILE_OFF 1024u
#define OUT_SMEM (TILE_OFF + NSTG * STG_B)       // 99328 B

__global__ void __launch_bounds__(128, 2) k_out_mma(const float* __restrict__ bo,
                                                    float* __restrict__ out)
{
    extern __shared__ char smem[];
    const uint32_t smem_base = smaddr(smem);
    const uint32_t fullb  = smem_base;
    const uint32_t emptyb = smem_base + 64;

    const int tid  = threadIdx.x;
    const int warp = tid >> 5;
    const int lane = tid & 31;
    const int wm   = warp >> 1;
    const int wn   = warp & 1;
    const int mt   = blockIdx.x;
    const int nt2  = blockIdx.y;

    if (tid == 0) {
#pragma unroll
        for (int s2 = 0; s2 < NSTG; s2++) {
            MBARRIER_INIT(fullb  + s2 * 8, 1);
            MBARRIER_INIT(emptyb + s2 * 8, 4);
        }
        FENCE_ASYNC_SHARED();
    }
    __syncthreads();

    const __half* gA = g_hA  + (size_t)mt * 16 * 4096;
    const __half* gB = g_WoB + (size_t)(nt2 >> 1) * 16 * 8192 + (size_t)(nt2 & 1) * 4096;

    auto issue = [&](int cc) {
        int st = cc % NSTG;
        uint32_t sa = smem_base + TILE_OFF + st * STG_B;
        MBARRIER_EXPECT_TX(fullb + st * 8, STG_B);
        bulk_g2s(sa,             gA + (size_t)cc * 4096, A_PANEL_B, fullb + st * 8);
        bulk_g2s(sa + A_PANEL_B, gB + (size_t)cc * 8192, B_PANEL_B, fullb + st * 8);
    };

    if (tid == 0) {
#pragma unroll
        for (int c = 0; c < NSTG; c++) issue(c);
    }

    float acc[4][8][4];
#pragma unroll
    for (int mi = 0; mi < 4; mi++)
#pragma unroll
        for (int ni = 0; ni < 8; ni++)
#pragma unroll
            for (int j = 0; j < 4; j++) acc[mi][ni][j] = 0.f;

#pragma unroll 1
    for (int c = 0; c < 16; c++) {
        const int st = c % NSTG;
        const int ph = (c / NSTG) & 1;
        MBARRIER_WAIT_PARITY(fullb + st * 8, ph);

        const uint32_t sa = smem_base + TILE_OFF + st * STG_B;
        const uint32_t sb = sa + A_PANEL_B;

        uint32_t af[2][4][4];
        uint32_t bf[2][4][4];
#pragma unroll
        for (int kk = 0; kk < 2; kk++) {
#pragma unroll
            for (int mi = 0; mi < 4; mi++)
                lds128(sa + (uint32_t)((((wm * 4 + mi) * 2 + kk) * 32 + lane) * 16),
                       af[kk][mi][0], af[kk][mi][1], af[kk][mi][2], af[kk][mi][3]);
#pragma unroll
            for (int np = 0; np < 4; np++)
                lds128(sb + (uint32_t)(((wn * 8 + kk * 4 + np) * 32 + lane) * 16),
                       bf[kk][np][0], bf[kk][np][1], bf[kk][np][2], bf[kk][np][3]);
        }
        if (elect_one_pred()) MBARRIER_ARRIVE(emptyb + st * 8);

#pragma unroll
        for (int kk = 0; kk < 2; kk++) {
#pragma unroll
            for (int mi = 0; mi < 4; mi++) {
#pragma unroll
                for (int np = 0; np < 4; np++) {
                    mma_f16(acc[mi][2 * np][0], acc[mi][2 * np][1],
                            acc[mi][2 * np][2], acc[mi][2 * np][3],
                            af[kk][mi][0], af[kk][mi][1], af[kk][mi][2], af[kk][mi][3],
                            bf[kk][np][0], bf[kk][np][1]);
                    mma_f16(acc[mi][2 * np + 1][0], acc[mi][2 * np + 1][1],
                            acc[mi][2 * np + 1][2], acc[mi][2 * np + 1][3],
                            af[kk][mi][0], af[kk][mi][1], af[kk][mi][2], af[kk][mi][3],
                            bf[kk][np][2], bf[kk][np][3]);
                }
            }
        }

        if (tid == 0 && c < 16 - NSTG) {
            MBARRIER_WAIT_PARITY(emptyb + st * 8, (c / NSTG) & 1);
            issue(c + NSTG);
        }
    }

    const int m0 = mt * 128 + wm * 64;
    const int n0 = nt2 * 128 + wn * 64;
#pragma unroll
    for (int ni = 0; ni < 8; ni++) {
        int ccol = n0 + ni * 8 + (lane & 3) * 2;
        float2 b2 = *(const float2*)(bo + ccol);
#pragma unroll
        for (int mi = 0; mi < 4; mi++) {
            int r = m0 + mi * 16 + (lane >> 2);
            float2 o0, o1;
            o0.x = acc[mi][ni][0] + b2.x;
            o0.y = acc[mi][ni][1] + b2.y;
            o1.x = acc[mi][ni][2] + b2.x;
            o1.y = acc[mi][ni][3] + b2.y;
            *(float2*)(out + (size_t)r * OUT_DIM + ccol)       = o0;
            *(float2*)(out + (size_t)(r + 8) * OUT_DIM + ccol) = o1;
        }
    }
}

// ============================================================================
extern "C" void kernel_launch(void* const* d_in, const int* in_sizes, int n_in,
                              void* d_out, int out_size)
{
    (void)in_sizes; (void)n_in; (void)out_size;
    const int*   x   = (const int*)d_in[0];
    const float* emb = (const float*)d_in[1];
    const float* Wh  = (const float*)d_in[2];
    const float* bh  = (const float*)d_in[3];
    const float* Wo  = (const float*)d_in[4];
    const float* bo  = (const float*)d_in[5];

    float* out = (float*)d_out;                       // [8192, 32000]
    float* hid = out + (size_t)MROWS * OUT_DIM;       // [8192, 512]

    cudaFuncSetAttribute(k_out_mma, cudaFuncAttributeMaxDynamicSharedMemorySize,
                         OUT_SMEM);

    k_xproj<<<dim3(4, 128), 256>>>(x, emb, Wh, bh);
    k_prepB<<<dim3(OUT_DIM / 256, LAT / 32), 256>>>(Wo);
    k_rnn<<<128, 256>>>(Wh, hid);
    k_prepA<<<dim3(MROWS / 128, LAT / 32), 256>>>(hid);
    k_out_mma<<<dim3(MROWS / 128, OUT_DIM / 128), 128, OUT_SMEM>>>(bo, out);
}

// round 11
// speedup vs baseline: 1.0214x; 1.0214x over previous
#include <cuda_runtime.h>
#include <cuda_fp16.h>
#include <cstdint>
#include <cstddef>

#define T_STEPS 256
#define BATCH   32
#define EMB     256
#define LAT     512
#define OUT_DIM 32000
#define MROWS   (T_STEPS * BATCH)   // 8192

// ---------------- device scratch (no allocations allowed) ------------------
__device__ float    g_xproj[(size_t)MROWS * LAT];      // 16 MB
__device__ __half   g_hA[(size_t)MROWS * LAT];         // 8 MB, A fragment-major fp16
__device__ __half   g_WoB[(size_t)OUT_DIM * LAT];      // 32.75 MB, B fragment-major fp16
__device__ unsigned g_cnt[8];                           // rnn barrier counters

// ---------------- helpers ----------------------------------------------------
__device__ __forceinline__ unsigned long long pack2(float a, float b) {
    unsigned long long r;
    asm("mov.b64 %0, {%1, %2};" : "=l"(r) : "f"(a), "f"(b));
    return r;
}
__device__ __forceinline__ void unpack2(unsigned long long v, float& a, float& b) {
    asm("mov.b64 {%0, %1}, %2;" : "=f"(a), "=f"(b) : "l"(v));
}
__device__ __forceinline__ void ffma2(unsigned long long& acc, unsigned long long h,
                                      unsigned long long w) {
    asm("fma.rn.f32x2 %0, %1, %2, %0;" : "+l"(acc) : "l"(h), "l"(w));
}
__device__ __forceinline__ uint32_t pack_h2(float lo, float hi) {
    __half2 h = __floats2half2_rn(lo, hi);
    return *(uint32_t*)&h;
}
__device__ __forceinline__ uint32_t smaddr(const void* p) {
    return (uint32_t)__cvta_generic_to_shared(p);
}
__device__ __forceinline__ uint32_t elect_one_pred() {
    uint32_t pred;
    asm volatile(
        "{\n\t.reg .pred p;\n\t"
        "elect.sync _|p, 0xFFFFFFFF;\n\t"
        "selp.b32 %0, 1, 0, p;\n\t}"
        : "=r"(pred));
    return pred;
}
__device__ __forceinline__ void lds128(uint32_t a, uint32_t& r0, uint32_t& r1,
                                       uint32_t& r2, uint32_t& r3) {
    asm volatile("ld.shared.v4.b32 {%0, %1, %2, %3}, [%4];"
                 : "=r"(r0), "=r"(r1), "=r"(r2), "=r"(r3) : "r"(a));
}
__device__ __forceinline__ void bulk_g2s(uint32_t dst, const void* src,
                                         uint32_t bytes, uint32_t mbar) {
    asm volatile(
        "cp.async.bulk.shared::cluster.global.mbarrier::complete_tx::bytes "
        "[%0], [%1], %2, [%3];"
        :: "r"(dst), "l"(src), "r"(bytes), "r"(mbar) : "memory");
}
__device__ __forceinline__ void red_release_add(unsigned* p, unsigned v) {
    asm volatile("red.release.gpu.global.add.u32 [%0], %1;"
                 :: "l"(p), "r"(v) : "memory");
}
__device__ __forceinline__ unsigned ld_acquire(const unsigned* p) {
    unsigned v;
    asm volatile("ld.global.acquire.gpu.u32 %0, [%1];" : "=r"(v) : "l"(p) : "memory");
    return v;
}
#define MBARRIER_INIT(mbar, cnt) \
    asm volatile("mbarrier.init.shared.b64 [%0], %1;" \
                 :: "r"((uint32_t)(mbar)), "r"((uint32_t)(cnt)) : "memory")
#define MBARRIER_ARRIVE(mbar) \
    asm volatile("mbarrier.arrive.shared.b64 _, [%0];" \
                 :: "r"((uint32_t)(mbar)) : "memory")
#define MBARRIER_EXPECT_TX(mbar, tx) \
    asm volatile("mbarrier.arrive.expect_tx.shared.b64 _, [%0], %1;" \
                 :: "r"((uint32_t)(mbar)), "r"((uint32_t)(tx)) : "memory")
#define MBARRIER_WAIT_PARITY(mbar, par) do {                                   \
    uint32_t _m = (uint32_t)(mbar);                                            \
    uint32_t _p = (uint32_t)(par);                                             \
    asm volatile(                                                              \
        "{\n\t.reg .pred P1;\n\t"                                              \
        "WL_%=:\n\t"                                                           \
        "mbarrier.try_wait.parity.acquire.cta.shared::cta.b64 P1, [%0], %1, 0x989680;\n\t" \
        "@P1 bra.uni WD_%=;\n\t"                                               \
        "bra.uni WL_%=;\n\t"                                                   \
        "WD_%=:\n\t}"                                                          \
        :: "r"(_m), "r"(_p) : "memory");                                       \
} while (0)
#define FENCE_ASYNC_SHARED() asm volatile("fence.proxy.async.shared::cta;" ::: "memory")

__device__ __forceinline__ void mma_f16(float& c0, float& c1, float& c2, float& c3,
                                        uint32_t a0, uint32_t a1, uint32_t a2, uint32_t a3,
                                        uint32_t b0, uint32_t b1) {
    asm volatile(
        "mma.sync.aligned.m16n8k16.row.col.f32.f16.f16.f32 "
        "{%0,%1,%2,%3}, {%4,%5,%6,%7}, {%8,%9}, {%0,%1,%2,%3};"
        : "+f"(c0), "+f"(c1), "+f"(c2), "+f"(c3)
        : "r"(a0), "r"(a1), "r"(a2), "r"(a3), "r"(b0), "r"(b1));
}

// ============================================================================
// Kernel 1: xproj = gather(emb, x) @ W_h[:256] + b_h  (fp32 SIMT)
// ============================================================================
__global__ void __launch_bounds__(256) k_xproj(const int* __restrict__ x,
                                               const float* __restrict__ emb,
                                               const float* __restrict__ Wh,
                                               const float* __restrict__ bh)
{
    __shared__ float As[64][36];
    __shared__ float Bs[32][132];
    __shared__ int   xs[64];

    const int tid = threadIdx.x;
    const int m0  = blockIdx.y * 64;
    const int n0  = blockIdx.x * 128;

    if (blockIdx.x == 0 && blockIdx.y == 0 && tid < 8) g_cnt[tid] = 0;

    if (tid < 64) xs[tid] = x[m0 + tid];
    __syncthreads();

    const int ty = tid >> 5;
    const int tx = tid & 31;

    float acc[8][4];
#pragma unroll
    for (int i = 0; i < 8; i++)
#pragma unroll
        for (int j = 0; j < 4; j++) acc[i][j] = 0.f;

    for (int k0 = 0; k0 < EMB; k0 += 32) {
#pragma unroll
        for (int q = 0; q < 2; q++) {
            int f = tid + q * 256;
            int r = f >> 3, c4 = f & 7;
            float4 v = *(const float4*)(emb + (size_t)xs[r] * EMB + k0 + c4 * 4);
            *(float4*)(&As[r][c4 * 4]) = v;
        }
#pragma unroll
        for (int q = 0; q < 4; q++) {
            int f = tid + q * 256;
            int r = f >> 5, c4 = f & 31;
            float4 v = *(const float4*)(Wh + (size_t)(k0 + r) * LAT + n0 + c4 * 4);
            *(float4*)(&Bs[r][c4 * 4]) = v;
        }
        __syncthreads();

#pragma unroll
        for (int kq = 0; kq < 8; kq++) {
            float bt[4][4];
#pragma unroll
            for (int kk = 0; kk < 4; kk++) {
                float4 t = *(float4*)(&Bs[kq * 4 + kk][tx * 4]);
                bt[kk][0] = t.x; bt[kk][1] = t.y; bt[kk][2] = t.z; bt[kk][3] = t.w;
            }
#pragma unroll
            for (int i = 0; i < 8; i++) {
                float4 a4 = *(float4*)(&As[ty * 8 + i][kq * 4]);
#pragma unroll
                for (int j = 0; j < 4; j++) {
                    acc[i][j] = fmaf(a4.x, bt[0][j],
                                fmaf(a4.y, bt[1][j],
                                fmaf(a4.z, bt[2][j],
                                fmaf(a4.w, bt[3][j], acc[i][j]))));
                }
            }
        }
        __syncthreads();
    }

    float4 bh4 = *(const float4*)(bh + n0 + tx * 4);
#pragma unroll
    for (int i = 0; i < 8; i++) {
        float4 o;
        o.x = acc[i][0] + bh4.x;
        o.y = acc[i][1] + bh4.y;
        o.z = acc[i][2] + bh4.z;
        o.w = acc[i][3] + bh4.w;
        *(float4*)(g_xproj + (size_t)(m0 + ty * 8 + i) * LAT + n0 + tx * 4) = o;
    }
}

// ============================================================================
// Kernel 1b: build g_WoB — B fragment-major fp16 for m16n8k16.
// ============================================================================
__global__ void __launch_bounds__(256) k_prepB(const float* __restrict__ Wo)
{
    const int nt = blockIdx.x, kt = blockIdx.y;
    const int w = threadIdx.x >> 5, lane = threadIdx.x & 31;
    __half* panel = g_WoB + ((size_t)nt * 16 + kt) * 8192;

#pragma unroll
    for (int bi = 0; bi < 4; bi++) {
        int b  = w * 4 + bi;                 // 0..31
        int wn = b >> 3, kk = (b >> 2) & 1, np = b & 3;
        int n0 = nt * 256 + wn * 64 + np * 16 + (lane >> 2);
        int k0 = kt * 32 + kk * 16 + (lane & 3) * 2;
        const float* base = Wo + (size_t)k0 * OUT_DIM + n0;
        uint4 v;
        v.x = pack_h2(base[0],                       base[(size_t)1 * OUT_DIM]);
        v.y = pack_h2(base[(size_t)8 * OUT_DIM],     base[(size_t)9 * OUT_DIM]);
        v.z = pack_h2(base[8],                       base[(size_t)1 * OUT_DIM + 8]);
        v.w = pack_h2(base[(size_t)8 * OUT_DIM + 8], base[(size_t)9 * OUT_DIM + 8]);
        *(uint4*)(panel + (size_t)b * 256 + lane * 8) = v;
    }
}

// ============================================================================
// Kernel 2: persistent recurrence (round-10 version).
// ============================================================================
__global__ void __launch_bounds__(256, 1) k_rnn(const float* __restrict__ Wh,
                                                float* __restrict__ hid)
{
    __shared__ ulonglong2 hsT[512];
    __shared__ float      red[8][4][32];

    const int tid  = threadIdx.x;
    const int s    = tid >> 5;
    const int c    = tid & 31;
    const int bgrp = blockIdx.x >> 4;
    const int cgrp = blockIdx.x & 15;
    const int b0   = bgrp * 4;
    const int col  = cgrp * 32 + c;

    float w[64];
#pragma unroll
    for (int i = 0; i < 64; i++)
        w[i] = Wh[(size_t)(EMB + s * 64 + i) * LAT + col];

    unsigned target = 0;
    for (int t = 0; t < T_STEPS; t++) {
        float xp = 0.f;
        if (tid < 128) {
            xp = __ldg(g_xproj + (size_t)(t * BATCH + b0 + (tid >> 5)) * LAT
                       + cgrp * 32 + (tid & 31));
        }

#pragma unroll
        for (int hq = 0; hq < 2; hq++) {
            int k = tid + hq * 256;
            float v0, v1, v2, v3;
            if (t == 0) {
                v0 = v1 = v2 = v3 = 0.f;
            } else {
                const float* hp = hid + (size_t)((t - 1) * BATCH + b0) * LAT + k;
                v0 = __ldcg(hp);
                v1 = __ldcg(hp + LAT);
                v2 = __ldcg(hp + 2 * LAT);
                v3 = __ldcg(hp + 3 * LAT);
            }
            hsT[k] = make_ulonglong2(pack2(v0, v1), pack2(v2, v3));
        }
        __syncthreads();

        unsigned long long acc01 = 0ull, acc23 = 0ull;
        const ulonglong2* hp = hsT + s * 64;
#pragma unroll
        for (int i = 0; i < 64; i++) {
            ulonglong2 hv = hp[i];
            unsigned long long w2 = pack2(w[i], w[i]);
            ffma2(acc01, hv.x, w2);
            ffma2(acc23, hv.y, w2);
        }
        float a0, a1, a2, a3;
        unpack2(acc01, a0, a1);
        unpack2(acc23, a2, a3);
        red[s][0][c] = a0;
        red[s][1][c] = a1;
        red[s][2][c] = a2;
        red[s][3][c] = a3;
        __syncthreads();

        if (tid < 128) {
            int bb = tid >> 5, cc = tid & 31;
            float v = xp;
#pragma unroll
            for (int ss = 0; ss < 8; ss++) v += red[ss][bb][cc];
            int colw = cgrp * 32 + cc;
            int rowi = t * BATCH + b0 + bb;
            v = fmaxf(v, 0.f);
            hid[(size_t)rowi * LAT + colw] = v;   // coalesced fp32 only
        }
        __syncthreads();

        target += 16;
        if (tid == 0) {
            red_release_add(&g_cnt[bgrp], 1u);
            while (ld_acquire(&g_cnt[bgrp]) < target) { }
        }
        __syncthreads();
    }
}

// ============================================================================
// Kernel 2b: k_prepA — build g_hA (fragment-major fp16) from hid, coalesced.
// ============================================================================
__global__ void __launch_bounds__(256) k_prepA(const float* __restrict__ hid)
{
    const int mt = blockIdx.x, kt = blockIdx.y;
    const int w = threadIdx.x >> 5, lane = threadIdx.x & 31;
    __half* panel = g_hA + ((size_t)mt * 16 + kt) * 4096;

#pragma unroll
    for (int kk = 0; kk < 2; kk++) {
        uint32_t r4[4];
#pragma unroll
        for (int j = 0; j < 4; j++) {
            int row   = mt * 128 + w * 16 + (lane >> 2) + 8 * (j & 1);
            int kbase = kt * 32 + kk * 16 + (lane & 3) * 2 + 8 * (j >> 1);
            float2 v = *(const float2*)(hid + (size_t)row * LAT + kbase);
            r4[j] = pack_h2(v.x, v.y);
        }
        *(uint4*)(panel + (size_t)(((w * 2 + kk) * 32 + lane) * 4) * 2) =
            make_uint4(r4[0], r4[1], r4[2], r4[3]);
    }
}

// ============================================================================
// Kernel 3: out = hid @ Wo + bo.  mma.sync fp16, fragment-major operands,
// cp.async.bulk 6-stage ring, 2 CTAs/SM. SOFTWARE-PIPELINED fragment loads:
// loads for the next kk-phase are issued while HMMAs of the current phase
// drain, so LDS/try_wait bubbles hide under tensor work.
// ============================================================================
#define NSTG 6
#define A_PANEL_B 8192u
#define B_PANEL_B 8192u
#define STG_B (A_PANEL_B + B_PANEL_B)            // 16384
#define TILE_OFF 1024u
#define OUT_SMEM (TILE_OFF + NSTG * STG_B)       // 99328 B

#define LOAD_FRAGS(afb, bfb, sa, sb, kkv)                                      \
    do {                                                                       \
        _Pragma("unroll")                                                      \
        for (int mi = 0; mi < 4; mi++)                                         \
            lds128((sa) + (uint32_t)((((wm * 4 + mi) * 2 + (kkv)) * 32 + lane) * 16), \
                   (afb)[mi][0], (afb)[mi][1], (afb)[mi][2], (afb)[mi][3]);    \
        _Pragma("unroll")                                                      \
        for (int np = 0; np < 4; np++)                                         \
            lds128((sb) + (uint32_t)(((wn * 8 + (kkv) * 4 + np) * 32 + lane) * 16), \
                   (bfb)[np][0], (bfb)[np][1], (bfb)[np][2], (bfb)[np][3]);    \
    } while (0)

#define DO_HMMAS(afb, bfb)                                                     \
    do {                                                                       \
        _Pragma("unroll")                                                      \
        for (int mi = 0; mi < 4; mi++) {                                       \
            _Pragma("unroll")                                                  \
            for (int np = 0; np < 4; np++) {                                   \
                mma_f16(acc[mi][2 * np][0], acc[mi][2 * np][1],                \
                        acc[mi][2 * np][2], acc[mi][2 * np][3],                \
                        (afb)[mi][0], (afb)[mi][1], (afb)[mi][2], (afb)[mi][3],\
                        (bfb)[np][0], (bfb)[np][1]);                           \
                mma_f16(acc[mi][2 * np + 1][0], acc[mi][2 * np + 1][1],        \
                        acc[mi][2 * np + 1][2], acc[mi][2 * np + 1][3],        \
                        (afb)[mi][0], (afb)[mi][1], (afb)[mi][2], (afb)[mi][3],\
                        (bfb)[np][2], (bfb)[np][3]);                           \
            }                                                                  \
        }                                                                      \
    } while (0)

__global__ void __launch_bounds__(128, 2) k_out_mma(const float* __restrict__ bo,
                                                    float* __restrict__ out)
{
    extern __shared__ char smem[];
    const uint32_t smem_base = smaddr(smem);
    const uint32_t fullb  = smem_base;
    const uint32_t emptyb = smem_base + 64;

    const int tid  = threadIdx.x;
    const int warp = tid >> 5;
    const int lane = tid & 31;
    const int wm   = warp >> 1;
    const int wn   = warp & 1;
    const int mt   = blockIdx.x;
    const int nt2  = blockIdx.y;

    if (tid == 0) {
#pragma unroll
        for (int s2 = 0; s2 < NSTG; s2++) {
            MBARRIER_INIT(fullb  + s2 * 8, 1);
            MBARRIER_INIT(emptyb + s2 * 8, 4);
        }
        FENCE_ASYNC_SHARED();
    }
    __syncthreads();

    const __half* gA = g_hA  + (size_t)mt * 16 * 4096;
    const __half* gB = g_WoB + (size_t)(nt2 >> 1) * 16 * 8192 + (size_t)(nt2 & 1) * 4096;

    auto issue = [&](int cc) {
        int st = cc % NSTG;
        uint32_t sa = smem_base + TILE_OFF + st * STG_B;
        MBARRIER_EXPECT_TX(fullb + st * 8, STG_B);
        bulk_g2s(sa,             gA + (size_t)cc * 4096, A_PANEL_B, fullb + st * 8);
        bulk_g2s(sa + A_PANEL_B, gB + (size_t)cc * 8192, B_PANEL_B, fullb + st * 8);
    };

    if (tid == 0) {
#pragma unroll
        for (int c = 0; c < NSTG; c++) issue(c);
    }

    float acc[4][8][4];
#pragma unroll
    for (int mi = 0; mi < 4; mi++)
#pragma unroll
        for (int ni = 0; ni < 8; ni++)
#pragma unroll
            for (int j = 0; j < 4; j++) acc[mi][ni][j] = 0.f;

    uint32_t af0[4][4], bf0[4][4];   // buffer 0: (c, kk0)
    uint32_t af1[4][4], bf1[4][4];   // buffer 1: (c, kk1)

    // ---- prologue: chunk 0 kk0 ----
    MBARRIER_WAIT_PARITY(fullb + 0, 0);
    {
        const uint32_t sa = smem_base + TILE_OFF;
        const uint32_t sb = sa + A_PANEL_B;
        LOAD_FRAGS(af0, bf0, sa, sb, 0);
    }

#pragma unroll 1
    for (int c = 0; c < 16; c++) {
        const int st = c % NSTG;
        const uint32_t sa = smem_base + TILE_OFF + st * STG_B;
        const uint32_t sb = sa + A_PANEL_B;

        // phase A: fill buf1 with (c, kk1), free stage, HMMA on buf0 (c, kk0)
        LOAD_FRAGS(af1, bf1, sa, sb, 1);
        if (elect_one_pred()) MBARRIER_ARRIVE(emptyb + st * 8);
        DO_HMMAS(af0, bf0);

        // phase B: wait next chunk, fill buf0 with (c+1, kk0), HMMA on buf1
        if (c < 15) {
            const int st2 = (c + 1) % NSTG;
            MBARRIER_WAIT_PARITY(fullb + st2 * 8, ((c + 1) / NSTG) & 1);
            const uint32_t sa2 = smem_base + TILE_OFF + st2 * STG_B;
            const uint32_t sb2 = sa2 + A_PANEL_B;
            LOAD_FRAGS(af0, bf0, sa2, sb2, 0);
        }
        DO_HMMAS(af1, bf1);

        if (tid == 0 && c < 16 - NSTG) {
            MBARRIER_WAIT_PARITY(emptyb + st * 8, (c / NSTG) & 1);
            issue(c + NSTG);
        }
    }

    // ---- epilogue: direct register -> global stores, + bias ----
    const int m0 = mt * 128 + wm * 64;
    const int n0 = nt2 * 128 + wn * 64;
#pragma unroll
    for (int ni = 0; ni < 8; ni++) {
        int ccol = n0 + ni * 8 + (lane & 3) * 2;
        float2 b2 = *(const float2*)(bo + ccol);
#pragma unroll
        for (int mi = 0; mi < 4; mi++) {
            int r = m0 + mi * 16 + (lane >> 2);
            float2 o0, o1;
            o0.x = acc[mi][ni][0] + b2.x;
            o0.y = acc[mi][ni][1] + b2.y;
            o1.x = acc[mi][ni][2] + b2.x;
            o1.y = acc[mi][ni][3] + b2.y;
            *(float2*)(out + (size_t)r * OUT_DIM + ccol)       = o0;
            *(float2*)(out + (size_t)(r + 8) * OUT_DIM + ccol) = o1;
        }
    }
}

// ============================================================================
extern "C" void kernel_launch(void* const* d_in, const int* in_sizes, int n_in,
                              void* d_out, int out_size)
{
    (void)in_sizes; (void)n_in; (void)out_size;
    const int*   x   = (const int*)d_in[0];
    const float* emb = (const float*)d_in[1];
    const float* Wh  = (const float*)d_in[2];
    const float* bh  = (const float*)d_in[3];
    const float* Wo  = (const float*)d_in[4];
    const float* bo  = (const float*)d_in[5];

    float* out = (float*)d_out;                       // [8192, 32000]
    float* hid = out + (size_t)MROWS * OUT_DIM;       // [8192, 512]

    cudaFuncSetAttribute(k_out_mma, cudaFuncAttributeMaxDynamicSharedMemorySize,
                         OUT_SMEM);

    k_xproj<<<dim3(4, 128), 256>>>(x, emb, Wh, bh);
    k_prepB<<<dim3(OUT_DIM / 256, LAT / 32), 256>>>(Wo);
    k_rnn<<<128, 256>>>(Wh, hid);
    k_prepA<<<dim3(MROWS / 128, LAT / 32), 256>>>(hid);
    k_out_mma<<<dim3(MROWS / 128, OUT_DIM / 128), 128, OUT_SMEM>>>(bo, out);
}

// round 12
// speedup vs baseline: 1.0986x; 1.0756x over previous
#include <cuda_runtime.h>
#include <cuda_fp16.h>
#include <cstdint>
#include <cstddef>

#define T_STEPS 256
#define BATCH   32
#define EMB     256
#define LAT     512
#define OUT_DIM 32000
#define MROWS   (T_STEPS * BATCH)   // 8192

// ---------------- device scratch (no allocations allowed) ------------------
__device__ float    g_xproj[(size_t)MROWS * LAT];      // 16 MB
__device__ __half   g_hA[(size_t)MROWS * LAT];         // 8 MB, A fragment-major fp16
__device__ __half   g_WoB[(size_t)OUT_DIM * LAT];      // 32.75 MB, B fragment-major fp16
__device__ unsigned g_cnt[8];                           // rnn barrier counters

// ---------------- helpers ----------------------------------------------------
__device__ __forceinline__ unsigned long long pack2(float a, float b) {
    unsigned long long r;
    asm("mov.b64 %0, {%1, %2};" : "=l"(r) : "f"(a), "f"(b));
    return r;
}
__device__ __forceinline__ void unpack2(unsigned long long v, float& a, float& b) {
    asm("mov.b64 {%0, %1}, %2;" : "=f"(a), "=f"(b) : "l"(v));
}
__device__ __forceinline__ void ffma2(unsigned long long& acc, unsigned long long h,
                                      unsigned long long w) {
    asm("fma.rn.f32x2 %0, %1, %2, %0;" : "+l"(acc) : "l"(h), "l"(w));
}
__device__ __forceinline__ uint32_t pack_h2(float lo, float hi) {
    __half2 h = __floats2half2_rn(lo, hi);
    return *(uint32_t*)&h;
}
__device__ __forceinline__ uint32_t smaddr(const void* p) {
    return (uint32_t)__cvta_generic_to_shared(p);
}
__device__ __forceinline__ uint32_t elect_one_pred() {
    uint32_t pred;
    asm volatile(
        "{\n\t.reg .pred p;\n\t"
        "elect.sync _|p, 0xFFFFFFFF;\n\t"
        "selp.b32 %0, 1, 0, p;\n\t}"
        : "=r"(pred));
    return pred;
}
__device__ __forceinline__ void lds128(uint32_t a, uint32_t& r0, uint32_t& r1,
                                       uint32_t& r2, uint32_t& r3) {
    asm volatile("ld.shared.v4.b32 {%0, %1, %2, %3}, [%4];"
                 : "=r"(r0), "=r"(r1), "=r"(r2), "=r"(r3) : "r"(a));
}
__device__ __forceinline__ void bulk_g2s(uint32_t dst, const void* src,
                                         uint32_t bytes, uint32_t mbar) {
    asm volatile(
        "cp.async.bulk.shared::cluster.global.mbarrier::complete_tx::bytes "
        "[%0], [%1], %2, [%3];"
        :: "r"(dst), "l"(src), "r"(bytes), "r"(mbar) : "memory");
}
__device__ __forceinline__ void red_release_add(unsigned* p, unsigned v) {
    asm volatile("red.release.gpu.global.add.u32 [%0], %1;"
                 :: "l"(p), "r"(v) : "memory");
}
__device__ __forceinline__ unsigned ld_acquire(const unsigned* p) {
    unsigned v;
    asm volatile("ld.global.acquire.gpu.u32 %0, [%1];" : "=r"(v) : "l"(p) : "memory");
    return v;
}
#define MBARRIER_INIT(mbar, cnt) \
    asm volatile("mbarrier.init.shared.b64 [%0], %1;" \
                 :: "r"((uint32_t)(mbar)), "r"((uint32_t)(cnt)) : "memory")
#define MBARRIER_ARRIVE(mbar) \
    asm volatile("mbarrier.arrive.shared.b64 _, [%0];" \
                 :: "r"((uint32_t)(mbar)) : "memory")
#define MBARRIER_EXPECT_TX(mbar, tx) \
    asm volatile("mbarrier.arrive.expect_tx.shared.b64 _, [%0], %1;" \
                 :: "r"((uint32_t)(mbar)), "r"((uint32_t)(tx)) : "memory")
#define MBARRIER_WAIT_PARITY(mbar, par) do {                                   \
    uint32_t _m = (uint32_t)(mbar);                                            \
    uint32_t _p = (uint32_t)(par);                                             \
    asm volatile(                                                              \
        "{\n\t.reg .pred P1;\n\t"                                              \
        "WL_%=:\n\t"                                                           \
        "mbarrier.try_wait.parity.acquire.cta.shared::cta.b64 P1, [%0], %1, 0x989680;\n\t" \
        "@P1 bra.uni WD_%=;\n\t"                                               \
        "bra.uni WL_%=;\n\t"                                                   \
        "WD_%=:\n\t}"                                                          \
        :: "r"(_m), "r"(_p) : "memory");                                       \
} while (0)
#define FENCE_ASYNC_SHARED() asm volatile("fence.proxy.async.shared::cta;" ::: "memory")
#define FENCE_PROXY_ASYNC() asm volatile("fence.proxy.async;" ::: "memory")

__device__ __forceinline__ void mma_f16(float& c0, float& c1, float& c2, float& c3,
                                        uint32_t a0, uint32_t a1, uint32_t a2, uint32_t a3,
                                        uint32_t b0, uint32_t b1) {
    asm volatile(
        "mma.sync.aligned.m16n8k16.row.col.f32.f16.f16.f32 "
        "{%0,%1,%2,%3}, {%4,%5,%6,%7}, {%8,%9}, {%0,%1,%2,%3};"
        : "+f"(c0), "+f"(c1), "+f"(c2), "+f"(c3)
        : "r"(a0), "r"(a1), "r"(a2), "r"(a3), "r"(b0), "r"(b1));
}

// Fragment-major index (in halfs) for A value at (row m, col k), fp16 m16n8k16.
__device__ __forceinline__ size_t hA_index_h(int m, int k) {
    int mt = m >> 7, mi16 = (m >> 4) & 7, r = m & 15;
    int kt = k >> 5, kk = (k >> 4) & 1, kb = k & 15;
    int lane = (r & 7) * 4 + ((kb >> 1) & 3);
    int j = (r >> 3) + 2 * (kb >> 3);
    int h = kb & 1;
    return ((size_t)mt * 16 + kt) * 4096
         + (size_t)((((mi16 * 2 + kk) * 32 + lane) * 4 + j) * 2 + h);
}

// ============================================================================
// Kernel 1: xproj = gather(emb, x) @ W_h[:256] + b_h  (fp32 SIMT)
// Also zeroes the rnn barrier counters (stream-ordered before k_fused).
// ============================================================================
__global__ void __launch_bounds__(256) k_xproj(const int* __restrict__ x,
                                               const float* __restrict__ emb,
                                               const float* __restrict__ Wh,
                                               const float* __restrict__ bh)
{
    __shared__ float As[64][36];
    __shared__ float Bs[32][132];
    __shared__ int   xs[64];

    const int tid = threadIdx.x;
    const int m0  = blockIdx.y * 64;
    const int n0  = blockIdx.x * 128;

    if (blockIdx.x == 0 && blockIdx.y == 0 && tid < 8) g_cnt[tid] = 0;

    if (tid < 64) xs[tid] = x[m0 + tid];
    __syncthreads();

    const int ty = tid >> 5;
    const int tx = tid & 31;

    float acc[8][4];
#pragma unroll
    for (int i = 0; i < 8; i++)
#pragma unroll
        for (int j = 0; j < 4; j++) acc[i][j] = 0.f;

    for (int k0 = 0; k0 < EMB; k0 += 32) {
#pragma unroll
        for (int q = 0; q < 2; q++) {
            int f = tid + q * 256;
            int r = f >> 3, c4 = f & 7;
            float4 v = *(const float4*)(emb + (size_t)xs[r] * EMB + k0 + c4 * 4);
            *(float4*)(&As[r][c4 * 4]) = v;
        }
#pragma unroll
        for (int q = 0; q < 4; q++) {
            int f = tid + q * 256;
            int r = f >> 5, c4 = f & 31;
            float4 v = *(const float4*)(Wh + (size_t)(k0 + r) * LAT + n0 + c4 * 4);
            *(float4*)(&Bs[r][c4 * 4]) = v;
        }
        __syncthreads();

#pragma unroll
        for (int kq = 0; kq < 8; kq++) {
            float bt[4][4];
#pragma unroll
            for (int kk = 0; kk < 4; kk++) {
                float4 t = *(float4*)(&Bs[kq * 4 + kk][tx * 4]);
                bt[kk][0] = t.x; bt[kk][1] = t.y; bt[kk][2] = t.z; bt[kk][3] = t.w;
            }
#pragma unroll
            for (int i = 0; i < 8; i++) {
                float4 a4 = *(float4*)(&As[ty * 8 + i][kq * 4]);
#pragma unroll
                for (int j = 0; j < 4; j++) {
                    acc[i][j] = fmaf(a4.x, bt[0][j],
                                fmaf(a4.y, bt[1][j],
                                fmaf(a4.z, bt[2][j],
                                fmaf(a4.w, bt[3][j], acc[i][j]))));
                }
            }
        }
        __syncthreads();
    }

    float4 bh4 = *(const float4*)(bh + n0 + tx * 4);
#pragma unroll
    for (int i = 0; i < 8; i++) {
        float4 o;
        o.x = acc[i][0] + bh4.x;
        o.y = acc[i][1] + bh4.y;
        o.z = acc[i][2] + bh4.z;
        o.w = acc[i][3] + bh4.w;
        *(float4*)(g_xproj + (size_t)(m0 + ty * 8 + i) * LAT + n0 + tx * 4) = o;
    }
}

// ============================================================================
// Kernel 1b: build g_WoB — B fragment-major fp16 for m16n8k16.
// ============================================================================
__global__ void __launch_bounds__(256) k_prepB(const float* __restrict__ Wo)
{
    const int nt = blockIdx.x, kt = blockIdx.y;
    const int w = threadIdx.x >> 5, lane = threadIdx.x & 31;
    __half* panel = g_WoB + ((size_t)nt * 16 + kt) * 8192;

#pragma unroll
    for (int bi = 0; bi < 4; bi++) {
        int b  = w * 4 + bi;                 // 0..31
        int wn = b >> 3, kk = (b >> 2) & 1, np = b & 3;
        int n0 = nt * 256 + wn * 64 + np * 16 + (lane >> 2);
        int k0 = kt * 32 + kk * 16 + (lane & 3) * 2;
        const float* base = Wo + (size_t)k0 * OUT_DIM + n0;
        uint4 v;
        v.x = pack_h2(base[0],                       base[(size_t)1 * OUT_DIM]);
        v.y = pack_h2(base[(size_t)8 * OUT_DIM],     base[(size_t)9 * OUT_DIM]);
        v.z = pack_h2(base[8],                       base[(size_t)1 * OUT_DIM + 8]);
        v.w = pack_h2(base[(size_t)8 * OUT_DIM + 8], base[(size_t)9 * OUT_DIM + 8]);
        *(uint4*)(panel + (size_t)b * 256 + lane * 8) = v;
    }
}

// ============================================================================
// FUSED kernel: blocks 0..127 = recurrence (128 thr: 4 k-slices x 32 cols,
// wv[128] regs, per-group L2 counter barrier, inline g_hA emit).
// Blocks 128.. = GEMM tiles (mt-ordered), gated on g_cnt[g] >= (mt+1)*64.
// ============================================================================
#define RNN_CTAS 128
#define NSTG 6
#define A_PANEL_B 8192u
#define B_PANEL_B 8192u
#define STG_B (A_PANEL_B + B_PANEL_B)            // 16384
#define TILE_OFF 1024u
#define OUT_SMEM (TILE_OFF + NSTG * STG_B)       // 99328 B

#define LOAD_FRAGS(afb, bfb, sa, sb, kkv)                                      \
    do {                                                                       \
        _Pragma("unroll")                                                      \
        for (int mi = 0; mi < 4; mi++)                                         \
            lds128((sa) + (uint32_t)((((wm * 4 + mi) * 2 + (kkv)) * 32 + lane) * 16), \
                   (afb)[mi][0], (afb)[mi][1], (afb)[mi][2], (afb)[mi][3]);    \
        _Pragma("unroll")                                                      \
        for (int np = 0; np < 4; np++)                                         \
            lds128((sb) + (uint32_t)(((wn * 8 + (kkv) * 4 + np) * 32 + lane) * 16), \
                   (bfb)[np][0], (bfb)[np][1], (bfb)[np][2], (bfb)[np][3]);    \
    } while (0)

#define DO_HMMAS(afb, bfb)                                                     \
    do {                                                                       \
        _Pragma("unroll")                                                      \
        for (int mi = 0; mi < 4; mi++) {                                       \
            _Pragma("unroll")                                                  \
            for (int np = 0; np < 4; np++) {                                   \
                mma_f16(acc[mi][2 * np][0], acc[mi][2 * np][1],                \
                        acc[mi][2 * np][2], acc[mi][2 * np][3],                \
                        (afb)[mi][0], (afb)[mi][1], (afb)[mi][2], (afb)[mi][3],\
                        (bfb)[np][0], (bfb)[np][1]);                           \
                mma_f16(acc[mi][2 * np + 1][0], acc[mi][2 * np + 1][1],        \
                        acc[mi][2 * np + 1][2], acc[mi][2 * np + 1][3],        \
                        (afb)[mi][0], (afb)[mi][1], (afb)[mi][2], (afb)[mi][3],\
                        (bfb)[np][2], (bfb)[np][3]);                           \
            }                                                                  \
        }                                                                      \
    } while (0)

__global__ void __launch_bounds__(128, 2) k_fused(const float* __restrict__ Wh,
                                                  const float* __restrict__ bo,
                                                  float* __restrict__ hid,
                                                  float* __restrict__ out)
{
    extern __shared__ char smem[];
    const int tid = threadIdx.x;
    const int bid = blockIdx.x;

    if (bid < RNN_CTAS) {
        // =================== recurrence path ===================
        ulonglong2* hsT = (ulonglong2*)smem;              // 512 x 16B = 8 KB
        float (*red)[4][32] = (float (*)[4][32])(smem + 8192);  // [4][4][32]

        const int s    = tid >> 5;            // 0..3  k-slice of 128
        const int c    = tid & 31;
        const int bgrp = bid >> 4;            // 0..7
        const int cgrp = bid & 15;            // 0..15
        const int b0   = bgrp * 4;
        const int col  = cgrp * 32 + c;

        float wv[128];
#pragma unroll
        for (int i = 0; i < 128; i++)
            wv[i] = Wh[(size_t)(EMB + s * 128 + i) * LAT + col];

        unsigned target = 0;
        for (int t = 0; t < T_STEPS; t++) {
            float xp = __ldg(g_xproj + (size_t)(t * BATCH + b0 + s) * LAT
                             + cgrp * 32 + c);

#pragma unroll
            for (int hq = 0; hq < 4; hq++) {
                int k = tid + hq * 128;
                float v0, v1, v2, v3;
                if (t == 0) {
                    v0 = v1 = v2 = v3 = 0.f;
                } else {
                    const float* hp = hid + (size_t)((t - 1) * BATCH + b0) * LAT + k;
                    v0 = __ldcg(hp);
                    v1 = __ldcg(hp + LAT);
                    v2 = __ldcg(hp + 2 * LAT);
                    v3 = __ldcg(hp + 3 * LAT);
                }
                hsT[k] = make_ulonglong2(pack2(v0, v1), pack2(v2, v3));
            }
            __syncthreads();

            unsigned long long acc01 = 0ull, acc23 = 0ull;
            const ulonglong2* hp = hsT + s * 128;
#pragma unroll
            for (int i = 0; i < 128; i++) {
                ulonglong2 hv = hp[i];
                unsigned long long w2 = pack2(wv[i], wv[i]);
                ffma2(acc01, hv.x, w2);
                ffma2(acc23, hv.y, w2);
            }
            float a0, a1, a2, a3;
            unpack2(acc01, a0, a1);
            unpack2(acc23, a2, a3);
            red[s][0][c] = a0;
            red[s][1][c] = a1;
            red[s][2][c] = a2;
            red[s][3][c] = a3;
            __syncthreads();

            {
                int bb = tid >> 5, cc = tid & 31;
                float v = xp;
#pragma unroll
                for (int ss = 0; ss < 4; ss++) v += red[ss][bb][cc];
                int colw = cgrp * 32 + cc;
                int rowi = t * BATCH + b0 + bb;
                v = fmaxf(v, 0.f);
                hid[(size_t)rowi * LAT + colw] = v;
                g_hA[hA_index_h(rowi, colw)] = __float2half_rn(v);
            }
            __syncthreads();

            target += 16;
            if (tid == 0) {
                red_release_add(&g_cnt[bgrp], 1u);
                while (ld_acquire(&g_cnt[bgrp]) < target) { }
            }
            __syncthreads();
        }
        return;
    }

    // =================== GEMM path ===================
    const int e    = bid - RNN_CTAS;
    const int mt   = e / (OUT_DIM / 128);     // 0..63 (slow index: available late)
    const int nt2  = e % (OUT_DIM / 128);     // 0..249

    const uint32_t smem_base = smaddr(smem);
    const uint32_t fullb  = smem_base;
    const uint32_t emptyb = smem_base + 64;

    const int warp = tid >> 5;
    const int lane = tid & 31;
    const int wm   = warp >> 1;
    const int wn   = warp & 1;

    if (tid == 0) {
#pragma unroll
        for (int s2 = 0; s2 < NSTG; s2++) {
            MBARRIER_INIT(fullb  + s2 * 8, 1);
            MBARRIER_INIT(emptyb + s2 * 8, 4);
        }
        FENCE_ASYNC_SHARED();
        // gate: all 8 batch groups must have finished timestep (mt+1)*4 - 1
        const unsigned need = (unsigned)(mt + 1) * 64u;
#pragma unroll 1
        for (int g = 0; g < 8; g++) {
            while (ld_acquire(&g_cnt[g]) < need) { __nanosleep(128); }
        }
    }
    __syncthreads();
    FENCE_PROXY_ASYNC();   // order acquired generic data before async-proxy reads

    const __half* gA = g_hA  + (size_t)mt * 16 * 4096;
    const __half* gB = g_WoB + (size_t)(nt2 >> 1) * 16 * 8192 + (size_t)(nt2 & 1) * 4096;

    auto issue = [&](int cc) {
        int st = cc % NSTG;
        uint32_t sa = smem_base + TILE_OFF + st * STG_B;
        MBARRIER_EXPECT_TX(fullb + st * 8, STG_B);
        bulk_g2s(sa,             gA + (size_t)cc * 4096, A_PANEL_B, fullb + st * 8);
        bulk_g2s(sa + A_PANEL_B, gB + (size_t)cc * 8192, B_PANEL_B, fullb + st * 8);
    };

    if (tid == 0) {
#pragma unroll
        for (int c = 0; c < NSTG; c++) issue(c);
    }

    float acc[4][8][4];
#pragma unroll
    for (int mi = 0; mi < 4; mi++)
#pragma unroll
        for (int ni = 0; ni < 8; ni++)
#pragma unroll
            for (int j = 0; j < 4; j++) acc[mi][ni][j] = 0.f;

    uint32_t af0[4][4], bf0[4][4];
    uint32_t af1[4][4], bf1[4][4];

    MBARRIER_WAIT_PARITY(fullb + 0, 0);
    {
        const uint32_t sa = smem_base + TILE_OFF;
        const uint32_t sb = sa + A_PANEL_B;
        LOAD_FRAGS(af0, bf0, sa, sb, 0);
    }

#pragma unroll 1
    for (int c = 0; c < 16; c++) {
        const int st = c % NSTG;
        const uint32_t sa = smem_base + TILE_OFF + st * STG_B;
        const uint32_t sb = sa + A_PANEL_B;

        LOAD_FRAGS(af1, bf1, sa, sb, 1);
        if (elect_one_pred()) MBARRIER_ARRIVE(emptyb + st * 8);
        DO_HMMAS(af0, bf0);

        if (c < 15) {
            const int st2 = (c + 1) % NSTG;
            MBARRIER_WAIT_PARITY(fullb + st2 * 8, ((c + 1) / NSTG) & 1);
            const uint32_t sa2 = smem_base + TILE_OFF + st2 * STG_B;
            const uint32_t sb2 = sa2 + A_PANEL_B;
            LOAD_FRAGS(af0, bf0, sa2, sb2, 0);
        }
        DO_HMMAS(af1, bf1);

        if (tid == 0 && c < 16 - NSTG) {
            MBARRIER_WAIT_PARITY(emptyb + st * 8, (c / NSTG) & 1);
            issue(c + NSTG);
        }
    }

    const int m0 = mt * 128 + wm * 64;
    const int n0 = nt2 * 128 + wn * 64;
#pragma unroll
    for (int ni = 0; ni < 8; ni++) {
        int ccol = n0 + ni * 8 + (lane & 3) * 2;
        float2 b2 = *(const float2*)(bo + ccol);
#pragma unroll
        for (int mi = 0; mi < 4; mi++) {
            int r = m0 + mi * 16 + (lane >> 2);
            float2 o0, o1;
            o0.x = acc[mi][ni][0] + b2.x;
            o0.y = acc[mi][ni][1] + b2.y;
            o1.x = acc[mi][ni][2] + b2.x;
            o1.y = acc[mi][ni][3] + b2.y;
            *(float2*)(out + (size_t)r * OUT_DIM + ccol)       = o0;
            *(float2*)(out + (size_t)(r + 8) * OUT_DIM + ccol) = o1;
        }
    }
}

// ============================================================================
extern "C" void kernel_launch(void* const* d_in, const int* in_sizes, int n_in,
                              void* d_out, int out_size)
{
    (void)in_sizes; (void)n_in; (void)out_size;
    const int*   x   = (const int*)d_in[0];
    const float* emb = (const float*)d_in[1];
    const float* Wh  = (const float*)d_in[2];
    const float* bh  = (const float*)d_in[3];
    const float* Wo  = (const float*)d_in[4];
    const float* bo  = (const float*)d_in[5];

    float* out = (float*)d_out;                       // [8192, 32000]
    float* hid = out + (size_t)MROWS * OUT_DIM;       // [8192, 512]

    cudaFuncSetAttribute(k_fused, cudaFuncAttributeMaxDynamicSharedMemorySize,
                         OUT_SMEM);

    k_xproj<<<dim3(4, 128), 256>>>(x, emb, Wh, bh);
    k_prepB<<<dim3(OUT_DIM / 256, LAT / 32), 256>>>(Wo);
    k_fused<<<RNN_CTAS + (MROWS / 128) * (OUT_DIM / 128), 128, OUT_SMEM>>>(
        Wh, bo, hid, out);
}

// round 13
// speedup vs baseline: 1.0995x; 1.0009x over previous
#include <cuda_runtime.h>
#include <cuda_fp16.h>
#include <cstdint>
#include <cstddef>

#define T_STEPS 256
#define BATCH   32
#define EMB     256
#define LAT     512
#define OUT_DIM 32000
#define MROWS   (T_STEPS * BATCH)   // 8192

// ---------------- device scratch (no allocations allowed) ------------------
__device__ float    g_xproj[(size_t)MROWS * LAT];      // 16 MB
__device__ __half   g_hA[(size_t)MROWS * LAT];         // 8 MB, A fragment-major fp16
__device__ __half   g_WoB[(size_t)OUT_DIM * LAT];      // 32.75 MB, B fragment-major fp16
__device__ unsigned g_cnt[8];                           // rnn barrier counters
__device__ unsigned g_xcnt[T_STEPS];                    // xproj per-timestep (to 4)
__device__ unsigned g_pcnt;                             // prepB counter (to 2000)

// ---------------- helpers ----------------------------------------------------
__device__ __forceinline__ unsigned long long pack2(float a, float b) {
    unsigned long long r;
    asm("mov.b64 %0, {%1, %2};" : "=l"(r) : "f"(a), "f"(b));
    return r;
}
__device__ __forceinline__ void unpack2(unsigned long long v, float& a, float& b) {
    asm("mov.b64 {%0, %1}, %2;" : "=f"(a), "=f"(b) : "l"(v));
}
__device__ __forceinline__ void ffma2(unsigned long long& acc, unsigned long long h,
                                      unsigned long long w) {
    asm("fma.rn.f32x2 %0, %1, %2, %0;" : "+l"(acc) : "l"(h), "l"(w));
}
__device__ __forceinline__ uint32_t pack_h2(float lo, float hi) {
    __half2 h = __floats2half2_rn(lo, hi);
    return *(uint32_t*)&h;
}
__device__ __forceinline__ uint32_t smaddr(const void* p) {
    return (uint32_t)__cvta_generic_to_shared(p);
}
__device__ __forceinline__ uint32_t elect_one_pred() {
    uint32_t pred;
    asm volatile(
        "{\n\t.reg .pred p;\n\t"
        "elect.sync _|p, 0xFFFFFFFF;\n\t"
        "selp.b32 %0, 1, 0, p;\n\t}"
        : "=r"(pred));
    return pred;
}
__device__ __forceinline__ void lds128(uint32_t a, uint32_t& r0, uint32_t& r1,
                                       uint32_t& r2, uint32_t& r3) {
    asm volatile("ld.shared.v4.b32 {%0, %1, %2, %3}, [%4];"
                 : "=r"(r0), "=r"(r1), "=r"(r2), "=r"(r3) : "r"(a));
}
__device__ __forceinline__ void bulk_g2s(uint32_t dst, const void* src,
                                         uint32_t bytes, uint32_t mbar) {
    asm volatile(
        "cp.async.bulk.shared::cluster.global.mbarrier::complete_tx::bytes "
        "[%0], [%1], %2, [%3];"
        :: "r"(dst), "l"(src), "r"(bytes), "r"(mbar) : "memory");
}
__device__ __forceinline__ void red_release_add(unsigned* p, unsigned v) {
    asm volatile("red.release.gpu.global.add.u32 [%0], %1;"
                 :: "l"(p), "r"(v) : "memory");
}
__device__ __forceinline__ unsigned ld_acquire(const unsigned* p) {
    unsigned v;
    asm volatile("ld.global.acquire.gpu.u32 %0, [%1];" : "=r"(v) : "l"(p) : "memory");
    return v;
}
#define MBARRIER_INIT(mbar, cnt) \
    asm volatile("mbarrier.init.shared.b64 [%0], %1;" \
                 :: "r"((uint32_t)(mbar)), "r"((uint32_t)(cnt)) : "memory")
#define MBARRIER_ARRIVE(mbar) \
    asm volatile("mbarrier.arrive.shared.b64 _, [%0];" \
                 :: "r"((uint32_t)(mbar)) : "memory")
#define MBARRIER_EXPECT_TX(mbar, tx) \
    asm volatile("mbarrier.arrive.expect_tx.shared.b64 _, [%0], %1;" \
                 :: "r"((uint32_t)(mbar)), "r"((uint32_t)(tx)) : "memory")
#define MBARRIER_WAIT_PARITY(mbar, par) do {                                   \
    uint32_t _m = (uint32_t)(mbar);                                            \
    uint32_t _p = (uint32_t)(par);                                             \
    asm volatile(                                                              \
        "{\n\t.reg .pred P1;\n\t"                                              \
        "WL_%=:\n\t"                                                           \
        "mbarrier.try_wait.parity.acquire.cta.shared::cta.b64 P1, [%0], %1, 0x989680;\n\t" \
        "@P1 bra.uni WD_%=;\n\t"                                               \
        "bra.uni WL_%=;\n\t"                                                   \
        "WD_%=:\n\t}"                                                          \
        :: "r"(_m), "r"(_p) : "memory");                                       \
} while (0)
#define FENCE_ASYNC_SHARED() asm volatile("fence.proxy.async.shared::cta;" ::: "memory")
#define FENCE_PROXY_ASYNC() asm volatile("fence.proxy.async;" ::: "memory")

__device__ __forceinline__ void mma_f16(float& c0, float& c1, float& c2, float& c3,
                                        uint32_t a0, uint32_t a1, uint32_t a2, uint32_t a3,
                                        uint32_t b0, uint32_t b1) {
    asm volatile(
        "mma.sync.aligned.m16n8k16.row.col.f32.f16.f16.f32 "
        "{%0,%1,%2,%3}, {%4,%5,%6,%7}, {%8,%9}, {%0,%1,%2,%3};"
        : "+f"(c0), "+f"(c1), "+f"(c2), "+f"(c3)
        : "r"(a0), "r"(a1), "r"(a2), "r"(a3), "r"(b0), "r"(b1));
}

// Fragment-major index (in halfs) for A value at (row m, col k), fp16 m16n8k16.
__device__ __forceinline__ size_t hA_index_h(int m, int k) {
    int mt = m >> 7, mi16 = (m >> 4) & 7, r = m & 15;
    int kt = k >> 5, kk = (k >> 4) & 1, kb = k & 15;
    int lane = (r & 7) * 4 + ((kb >> 1) & 3);
    int j = (r >> 3) + 2 * (kb >> 3);
    int h = kb & 1;
    return ((size_t)mt * 16 + kt) * 4096
         + (size_t)((((mi16 * 2 + kk) * 32 + lane) * 4 + j) * 2 + h);
}

// ============================================================================
// k_init: zero all counters (runs each graph replay, before k_fused).
// ============================================================================
__global__ void k_init()
{
    int t = threadIdx.x;
    if (t < 8) g_cnt[t] = 0;
    if (t == 8) g_pcnt = 0;
    if (t < T_STEPS) g_xcnt[t] = 0;
}

// ============================================================================
// FUSED kernel, 128 threads/CTA, 2 CTAs/SM.
// blocks [0,128)        : recurrence (gated per-step on xproj counters)
// blocks [128,1152)     : xproj tiles 32m x 128n (m-tile == timestep)
// blocks [1152,3152)    : prepB tiles (g_WoB fragment-major fp16)
// blocks [3152,19152)   : GEMM tiles (gated on prepB done + rnn progress)
// ============================================================================
#define RNN_CTAS   128
#define XP_CTAS    1024
#define PB_CTAS    2000
#define XP_BASE    RNN_CTAS
#define PB_BASE    (XP_BASE + XP_CTAS)
#define GEMM_BASE  (PB_BASE + PB_CTAS)

#define NSTG 6
#define A_PANEL_B 8192u
#define B_PANEL_B 8192u
#define STG_B (A_PANEL_B + B_PANEL_B)            // 16384
#define TILE_OFF 1024u
#define OUT_SMEM (TILE_OFF + NSTG * STG_B)       // 99328 B

#define LOAD_FRAGS(afb, bfb, sa, sb, kkv)                                      \
    do {                                                                       \
        _Pragma("unroll")                                                      \
        for (int mi = 0; mi < 4; mi++)                                         \
            lds128((sa) + (uint32_t)((((wm * 4 + mi) * 2 + (kkv)) * 32 + lane) * 16), \
                   (afb)[mi][0], (afb)[mi][1], (afb)[mi][2], (afb)[mi][3]);    \
        _Pragma("unroll")                                                      \
        for (int np = 0; np < 4; np++)                                         \
            lds128((sb) + (uint32_t)(((wn * 8 + (kkv) * 4 + np) * 32 + lane) * 16), \
                   (bfb)[np][0], (bfb)[np][1], (bfb)[np][2], (bfb)[np][3]);    \
    } while (0)

#define DO_HMMAS(afb, bfb)                                                     \
    do {                                                                       \
        _Pragma("unroll")                                                      \
        for (int mi = 0; mi < 4; mi++) {                                       \
            _Pragma("unroll")                                                  \
            for (int np = 0; np < 4; np++) {                                   \
                mma_f16(acc[mi][2 * np][0], acc[mi][2 * np][1],                \
                        acc[mi][2 * np][2], acc[mi][2 * np][3],                \
                        (afb)[mi][0], (afb)[mi][1], (afb)[mi][2], (afb)[mi][3],\
                        (bfb)[np][0], (bfb)[np][1]);                           \
                mma_f16(acc[mi][2 * np + 1][0], acc[mi][2 * np + 1][1],        \
                        acc[mi][2 * np + 1][2], acc[mi][2 * np + 1][3],        \
                        (afb)[mi][0], (afb)[mi][1], (afb)[mi][2], (afb)[mi][3],\
                        (bfb)[np][2], (bfb)[np][3]);                           \
            }                                                                  \
        }                                                                      \
    } while (0)

__global__ void __launch_bounds__(128, 2) k_fused(const int* __restrict__ x,
                                                  const float* __restrict__ emb,
                                                  const float* __restrict__ Wh,
                                                  const float* __restrict__ bh,
                                                  const float* __restrict__ Wo,
                                                  const float* __restrict__ bo,
                                                  float* __restrict__ hid,
                                                  float* __restrict__ out)
{
    extern __shared__ char smem[];
    const int tid = threadIdx.x;
    const int bid = blockIdx.x;

    if (bid < RNN_CTAS) {
        // =================== recurrence path ===================
        ulonglong2* hsT = (ulonglong2*)smem;                     // 8 KB
        float (*red)[4][32] = (float (*)[4][32])(smem + 8192);   // [4][4][32]

        const int s    = tid >> 5;            // 0..3  k-slice of 128
        const int c    = tid & 31;
        const int bgrp = bid >> 4;            // 0..7
        const int cgrp = bid & 15;            // 0..15
        const int b0   = bgrp * 4;
        const int col  = cgrp * 32 + c;

        float wv[128];
#pragma unroll
        for (int i = 0; i < 128; i++)
            wv[i] = Wh[(size_t)(EMB + s * 128 + i) * LAT + col];

        // gate: xproj for timestep 0 ready
        if (tid == 0) {
            while (ld_acquire(&g_xcnt[0]) < 4u) { }
        }
        __syncthreads();

        unsigned target = 0;
        for (int t = 0; t < T_STEPS; t++) {
            float xp = __ldcg(g_xproj + (size_t)(t * BATCH + b0 + s) * LAT
                              + cgrp * 32 + c);

#pragma unroll
            for (int hq = 0; hq < 4; hq++) {
                int k = tid + hq * 128;
                float v0, v1, v2, v3;
                if (t == 0) {
                    v0 = v1 = v2 = v3 = 0.f;
                } else {
                    const float* hp = hid + (size_t)((t - 1) * BATCH + b0) * LAT + k;
                    v0 = __ldcg(hp);
                    v1 = __ldcg(hp + LAT);
                    v2 = __ldcg(hp + 2 * LAT);
                    v3 = __ldcg(hp + 3 * LAT);
                }
                hsT[k] = make_ulonglong2(pack2(v0, v1), pack2(v2, v3));
            }
            __syncthreads();

            unsigned long long acc01 = 0ull, acc23 = 0ull;
            const ulonglong2* hp = hsT + s * 128;
#pragma unroll
            for (int i = 0; i < 128; i++) {
                ulonglong2 hv = hp[i];
                unsigned long long w2 = pack2(wv[i], wv[i]);
                ffma2(acc01, hv.x, w2);
                ffma2(acc23, hv.y, w2);
            }
            float a0, a1, a2, a3;
            unpack2(acc01, a0, a1);
            unpack2(acc23, a2, a3);
            red[s][0][c] = a0;
            red[s][1][c] = a1;
            red[s][2][c] = a2;
            red[s][3][c] = a3;
            __syncthreads();

            {
                int bb = tid >> 5, cc = tid & 31;
                float v = xp;
#pragma unroll
                for (int ss = 0; ss < 4; ss++) v += red[ss][bb][cc];
                int colw = cgrp * 32 + cc;
                int rowi = t * BATCH + b0 + bb;
                v = fmaxf(v, 0.f);
                hid[(size_t)rowi * LAT + colw] = v;
                g_hA[hA_index_h(rowi, colw)] = __float2half_rn(v);
            }
            __syncthreads();

            target += 16;
            if (tid == 0) {
                red_release_add(&g_cnt[bgrp], 1u);
                while (ld_acquire(&g_cnt[bgrp]) < target) { }
                if (t + 1 < T_STEPS) {
                    while (ld_acquire(&g_xcnt[t + 1]) < 4u) { }
                }
            }
            __syncthreads();
        }
        return;
    }

    if (bid < PB_BASE) {
        // =================== xproj path: tile 32m x 128n ===================
        const int e  = bid - XP_BASE;
        const int mt = e >> 2;            // == timestep t (early blocks first)
        const int nt = e & 3;
        const int m0 = mt * 32;
        const int n0 = nt * 128;

        float (*As)[36]  = (float (*)[36])smem;                   // 32x36
        float (*Bs)[132] = (float (*)[132])(smem + 32 * 36 * 4);  // 32x132
        int*  xs         = (int*)(smem + 32 * 36 * 4 + 32 * 132 * 4);

        if (tid < 32) xs[tid] = x[m0 + tid];
        __syncthreads();

        const int ty = tid >> 5;   // 0..3
        const int tx = tid & 31;

        float acc[8][4];
#pragma unroll
        for (int i = 0; i < 8; i++)
#pragma unroll
            for (int j = 0; j < 4; j++) acc[i][j] = 0.f;

        for (int k0 = 0; k0 < EMB; k0 += 32) {
#pragma unroll
            for (int q = 0; q < 2; q++) {           // A: 32x32 = 256 f4
                int f = tid + q * 128;
                int r = f >> 3, c4 = f & 7;
                float4 v = *(const float4*)(emb + (size_t)xs[r] * EMB + k0 + c4 * 4);
                *(float4*)(&As[r][c4 * 4]) = v;
            }
#pragma unroll
            for (int q = 0; q < 8; q++) {           // B: 32x128 = 1024 f4
                int f = tid + q * 128;
                int r = f >> 5, c4 = f & 31;
                float4 v = *(const float4*)(Wh + (size_t)(k0 + r) * LAT + n0 + c4 * 4);
                *(float4*)(&Bs[r][c4 * 4]) = v;
            }
            __syncthreads();

#pragma unroll
            for (int kq = 0; kq < 8; kq++) {
                float bt[4][4];
#pragma unroll
                for (int kk = 0; kk < 4; kk++) {
                    float4 tv = *(float4*)(&Bs[kq * 4 + kk][tx * 4]);
                    bt[kk][0] = tv.x; bt[kk][1] = tv.y; bt[kk][2] = tv.z; bt[kk][3] = tv.w;
                }
#pragma unroll
                for (int i = 0; i < 8; i++) {
                    float4 a4 = *(float4*)(&As[ty * 8 + i][kq * 4]);
#pragma unroll
                    for (int j = 0; j < 4; j++) {
                        acc[i][j] = fmaf(a4.x, bt[0][j],
                                    fmaf(a4.y, bt[1][j],
                                    fmaf(a4.z, bt[2][j],
                                    fmaf(a4.w, bt[3][j], acc[i][j]))));
                    }
                }
            }
            __syncthreads();
        }

        float4 bh4 = *(const float4*)(bh + n0 + tx * 4);
#pragma unroll
        for (int i = 0; i < 8; i++) {
            float4 o;
            o.x = acc[i][0] + bh4.x;
            o.y = acc[i][1] + bh4.y;
            o.z = acc[i][2] + bh4.z;
            o.w = acc[i][3] + bh4.w;
            *(float4*)(g_xproj + (size_t)(m0 + ty * 8 + i) * LAT + n0 + tx * 4) = o;
        }
        __syncthreads();
        if (tid == 0) red_release_add(&g_xcnt[mt], 1u);
        return;
    }

    if (bid < GEMM_BASE) {
        // =================== prepB path ===================
        const int e  = bid - PB_BASE;
        const int nt = e >> 4;             // 0..124
        const int kt = e & 15;             // 0..15
        const int w = tid >> 5, lane = tid & 31;
        __half* panel = g_WoB + ((size_t)nt * 16 + kt) * 8192;

#pragma unroll
        for (int bi = 0; bi < 8; bi++) {
            int b  = w * 8 + bi;             // 0..31
            int wn = b >> 3, kk = (b >> 2) & 1, np = b & 3;
            int n0 = nt * 256 + wn * 64 + np * 16 + (lane >> 2);
            int k0 = kt * 32 + kk * 16 + (lane & 3) * 2;
            const float* base = Wo + (size_t)k0 * OUT_DIM + n0;
            uint4 v;
            v.x = pack_h2(base[0],                       base[(size_t)1 * OUT_DIM]);
            v.y = pack_h2(base[(size_t)8 * OUT_DIM],     base[(size_t)9 * OUT_DIM]);
            v.z = pack_h2(base[8],                       base[(size_t)1 * OUT_DIM + 8]);
            v.w = pack_h2(base[(size_t)8 * OUT_DIM + 8], base[(size_t)9 * OUT_DIM + 8]);
            *(uint4*)(panel + (size_t)b * 256 + lane * 8) = v;
        }
        __syncthreads();
        if (tid == 0) red_release_add(&g_pcnt, 1u);
        return;
    }

    // =================== GEMM path ===================
    const int e    = bid - GEMM_BASE;
    const int mt   = e / (OUT_DIM / 128);     // 0..63
    const int nt2  = e % (OUT_DIM / 128);     // 0..249

    const uint32_t smem_base = smaddr(smem);
    const uint32_t fullb  = smem_base;
    const uint32_t emptyb = smem_base + 64;

    const int warp = tid >> 5;
    const int lane = tid & 31;
    const int wm   = warp >> 1;
    const int wn   = warp & 1;

    if (tid == 0) {
#pragma unroll
        for (int s2 = 0; s2 < NSTG; s2++) {
            MBARRIER_INIT(fullb  + s2 * 8, 1);
            MBARRIER_INIT(emptyb + s2 * 8, 4);
        }
        FENCE_ASYNC_SHARED();
        // gate 1: prepB complete
        while (ld_acquire(&g_pcnt) < (unsigned)PB_CTAS) { __nanosleep(128); }
        // gate 2: rnn progress — all 8 groups past timestep (mt+1)*4 - 1
        const unsigned need = (unsigned)(mt + 1) * 64u;
#pragma unroll 1
        for (int g = 0; g < 8; g++) {
            while (ld_acquire(&g_cnt[g]) < need) { __nanosleep(128); }
        }
    }
    __syncthreads();
    FENCE_PROXY_ASYNC();   // order acquired generic data before async-proxy reads

    const __half* gA = g_hA  + (size_t)mt * 16 * 4096;
    const __half* gB = g_WoB + (size_t)(nt2 >> 1) * 16 * 8192 + (size_t)(nt2 & 1) * 4096;

    auto issue = [&](int cc) {
        int st = cc % NSTG;
        uint32_t sa = smem_base + TILE_OFF + st * STG_B;
        MBARRIER_EXPECT_TX(fullb + st * 8, STG_B);
        bulk_g2s(sa,             gA + (size_t)cc * 4096, A_PANEL_B, fullb + st * 8);
        bulk_g2s(sa + A_PANEL_B, gB + (size_t)cc * 8192, B_PANEL_B, fullb + st * 8);
    };

    if (tid == 0) {
#pragma unroll
        for (int c = 0; c < NSTG; c++) issue(c);
    }

    float acc[4][8][4];
#pragma unroll
    for (int mi = 0; mi < 4; mi++)
#pragma unroll
        for (int ni = 0; ni < 8; ni++)
#pragma unroll
            for (int j = 0; j < 4; j++) acc[mi][ni][j] = 0.f;

    uint32_t af0[4][4], bf0[4][4];
    uint32_t af1[4][4], bf1[4][4];

    MBARRIER_WAIT_PARITY(fullb + 0, 0);
    {
        const uint32_t sa = smem_base + TILE_OFF;
        const uint32_t sb = sa + A_PANEL_B;
        LOAD_FRAGS(af0, bf0, sa, sb, 0);
    }

#pragma unroll 1
    for (int c = 0; c < 16; c++) {
        const int st = c % NSTG;
        const uint32_t sa = smem_base + TILE_OFF + st * STG_B;
        const uint32_t sb = sa + A_PANEL_B;

        LOAD_FRAGS(af1, bf1, sa, sb, 1);
        if (elect_one_pred()) MBARRIER_ARRIVE(emptyb + st * 8);
        DO_HMMAS(af0, bf0);

        if (c < 15) {
            const int st2 = (c + 1) % NSTG;
            MBARRIER_WAIT_PARITY(fullb + st2 * 8, ((c + 1) / NSTG) & 1);
            const uint32_t sa2 = smem_base + TILE_OFF + st2 * STG_B;
            const uint32_t sb2 = sa2 + A_PANEL_B;
            LOAD_FRAGS(af0, bf0, sa2, sb2, 0);
        }
        DO_HMMAS(af1, bf1);

        if (tid == 0 && c < 16 - NSTG) {
            MBARRIER_WAIT_PARITY(emptyb + st * 8, (c / NSTG) & 1);
            issue(c + NSTG);
        }
    }

    const int m0 = mt * 128 + wm * 64;
    const int n0 = nt2 * 128 + wn * 64;
#pragma unroll
    for (int ni = 0; ni < 8; ni++) {
        int ccol = n0 + ni * 8 + (lane & 3) * 2;
        float2 b2 = *(const float2*)(bo + ccol);
#pragma unroll
        for (int mi = 0; mi < 4; mi++) {
            int r = m0 + mi * 16 + (lane >> 2);
            float2 o0, o1;
            o0.x = acc[mi][ni][0] + b2.x;
            o0.y = acc[mi][ni][1] + b2.y;
            o1.x = acc[mi][ni][2] + b2.x;
            o1.y = acc[mi][ni][3] + b2.y;
            *(float2*)(out + (size_t)r * OUT_DIM + ccol)       = o0;
            *(float2*)(out + (size_t)(r + 8) * OUT_DIM + ccol) = o1;
        }
    }
}

// ============================================================================
extern "C" void kernel_launch(void* const* d_in, const int* in_sizes, int n_in,
                              void* d_out, int out_size)
{
    (void)in_sizes; (void)n_in; (void)out_size;
    const int*   x   = (const int*)d_in[0];
    const float* emb = (const float*)d_in[1];
    const float* Wh  = (const float*)d_in[2];
    const float* bh  = (const float*)d_in[3];
    const float* Wo  = (const float*)d_in[4];
    const float* bo  = (const float*)d_in[5];

    float* out = (float*)d_out;                       // [8192, 32000]
    float* hid = out + (size_t)MROWS * OUT_DIM;       // [8192, 512]

    cudaFuncSetAttribute(k_fused, cudaFuncAttributeMaxDynamicSharedMemorySize,
                         OUT_SMEM);

    k_init<<<1, 256>>>();
    k_fused<<<GEMM_BASE + (MROWS / 128) * (OUT_DIM / 128), 128, OUT_SMEM>>>(
        x, emb, Wh, bh, Wo, bo, hid, out);
}